// round 15
// baseline (speedup 1.0000x reference)
#include <cuda_runtime.h>
#include <cuda_fp16.h>
#include <math.h>
#include <stdint.h>

#define BB 2
#define NSEQ 2048
#define DD 1024
#define NH 16
#define HS 64
#define MM (BB*NSEQ)   // 4096 rows

// ---------------- scratch (allocation-free, __device__ globals) ----------------
__device__ __align__(16) __half g_xn [(size_t)MM*DD];
__device__ __align__(16) __half g_qkv[(size_t)MM*3*DD];
__device__ __align__(16) __half g_oh [(size_t)MM*DD];
__device__ float g_x1 [(size_t)MM*DD];
__device__ __align__(16) __half g_xn2[(size_t)MM*DD];
__device__ __align__(16) __half g_y  [(size_t)MM*2*DD];
__device__ __align__(16) __half g_wqkvh[(size_t)3*DD*DD];
__device__ __align__(16) __half g_wouth[(size_t)DD*DD];
__device__ __align__(16) __half g_w1h  [(size_t)2*DD*DD];
__device__ __align__(16) __half g_w2h  [(size_t)DD*2*DD];

__device__ __forceinline__ float gelu_tanh(float x){
    float u = 0.7978845608028654f * (x + 0.044715f*x*x*x);
    float t = 1.0f - 2.0f/(__expf(2.0f*u)+1.0f);
    return 0.5f*x*(1.0f+t);
}

__device__ __forceinline__ void cp_async16(void* smem, const void* gmem){
    unsigned s = (unsigned)__cvta_generic_to_shared(smem);
    asm volatile("cp.async.cg.shared.global [%0], [%1], 16;" :: "r"(s), "l"(gmem));
}
__device__ __forceinline__ void cp_commit(){ asm volatile("cp.async.commit_group;"); }
template<int N> __device__ __forceinline__ void cp_wait(){ asm volatile("cp.async.wait_group %0;" :: "n"(N)); }

__device__ __forceinline__ void mma_f16(float c[4], uint32_t a0, uint32_t a1,
                                        uint32_t a2, uint32_t a3,
                                        uint32_t b0, uint32_t b1){
    asm volatile(
        "mma.sync.aligned.m16n8k16.row.col.f32.f16.f16.f32 "
        "{%0,%1,%2,%3},{%4,%5,%6,%7},{%8,%9},{%0,%1,%2,%3};"
        : "+f"(c[0]), "+f"(c[1]), "+f"(c[2]), "+f"(c[3])
        : "r"(a0), "r"(a1), "r"(a2), "r"(a3), "r"(b0), "r"(b1));
}

// ---------------- merged weight prep: 4 transposes, one launch ----------------
// flattened 1D grid; each segment handles one weight, 32x32 tiles.
__global__ __launch_bounds__(256) void wtrans_all_kernel(
    const float* __restrict__ W0, __half* __restrict__ O0,   // wqkv  K=DD,  N=3DD  (96x32 tiles = 3072)
    const float* __restrict__ W1, __half* __restrict__ O1,   // wout  K=DD,  N=DD   (32x32 = 1024)
    const float* __restrict__ W2, __half* __restrict__ O2,   // w1    K=DD,  N=2DD  (64x32 = 2048)
    const float* __restrict__ W3, __half* __restrict__ O3)   // w2    K=2DD, N=DD   (32x64 = 2048)
{
    __shared__ float tile[32][33];
    int blk = blockIdx.x;
    const float* W; __half* O; int K, N, nbx;
    if (blk < 3072)      { W=W0; O=O0; K=DD;   N=3*DD; nbx=96; }
    else if (blk < 4096) { W=W1; O=O1; K=DD;   N=DD;   nbx=32; blk -= 3072; }
    else if (blk < 6144) { W=W2; O=O2; K=DD;   N=2*DD; nbx=64; blk -= 4096; }
    else                 { W=W3; O=O3; K=2*DD; N=DD;   nbx=32; blk -= 6144; }
    const int n0 = (blk % nbx)*32;
    const int k0 = (blk / nbx)*32;
    const int tx = threadIdx.x & 31, ty = threadIdx.x >> 5;
    for (int r = ty; r < 32; r += 8)
        tile[r][tx] = W[(size_t)(k0+r)*N + n0 + tx];
    __syncthreads();
    for (int r = ty; r < 32; r += 8)
        O[(size_t)(n0+r)*K + k0 + tx] = __float2half_rn(tile[tx][r]);
}

// ---------------- LayerNorm -> fp16 ----------------
__global__ __launch_bounds__(256) void ln_kernel(const float* __restrict__ x,
        const float* __restrict__ sc, const float* __restrict__ bi,
        __half* __restrict__ out)
{
    const int row = blockIdx.x;
    const int t = threadIdx.x;
    const float4 v = ((const float4*)(x + (size_t)row*DD))[t];
    float s  = v.x+v.y+v.z+v.w;
    float sq = v.x*v.x+v.y*v.y+v.z*v.z+v.w*v.w;
    #pragma unroll
    for (int o=16;o>0;o>>=1){
        s  += __shfl_xor_sync(0xffffffffu,s ,o);
        sq += __shfl_xor_sync(0xffffffffu,sq,o);
    }
    __shared__ float ss[8], sqs[8];
    const int warp=t>>5, lane=t&31;
    if (lane==0){ ss[warp]=s; sqs[warp]=sq; }
    __syncthreads();
    if (t==0){
        float a=0.f,b=0.f;
        #pragma unroll
        for(int i=0;i<8;i++){a+=ss[i]; b+=sqs[i];}
        ss[0]=a; sqs[0]=b;
    }
    __syncthreads();
    const float mean = ss[0]*(1.0f/DD);
    const float var  = sqs[0]*(1.0f/DD) - mean*mean;
    const float inv  = rsqrtf(var + 1e-6f);
    const float4 sc4 = ((const float4*)sc)[t];
    const float4 bi4 = ((const float4*)bi)[t];
    __half2* p = (__half2*)(out + (size_t)row*DD + 4*t);
    p[0] = __floats2half2_rn((v.x-mean)*inv*sc4.x + bi4.x,
                             (v.y-mean)*inv*sc4.y + bi4.y);
    p[1] = __floats2half2_rn((v.z-mean)*inv*sc4.z + bi4.z,
                             (v.w-mean)*inv*sc4.w + bi4.w);
}

#define HSTR 40
#define NSTG 3

// ---------------- THIN fp16 GEMM: CTA 128x128, warp 32x64, 2 CTA/SM ----------------
template<int EPI>
__global__ __launch_bounds__(256,2) void hgemm_thin(
    const __half* __restrict__ A, const __half* __restrict__ B,
    float* __restrict__ C, __half* __restrict__ Ch, int M, int N, int K,
    const float* __restrict__ bias, const float* __restrict__ res)
{
    extern __shared__ __half smh[];
    __half (*As)[128][HSTR] = (__half(*)[128][HSTR])smh;
    __half (*Bs)[128][HSTR] = (__half(*)[128][HSTR])(smh + (size_t)NSTG*128*HSTR);

    const int tid  = threadIdx.x;
    const int lane = tid & 31;
    const int warp = tid >> 5;
    const int wm = warp >> 1;
    const int wn = warp & 1;
    const int mB = wm*32;
    const int nB = wn*64;
    const int bm = blockIdx.y*128;
    const int bn = blockIdx.x*128;

    const int lr = tid >> 1;
    const int c0 = (tid & 1);

    const __half* Ag = A + (size_t)(bm + lr)*K + c0*8;
    const __half* Bg = B + (size_t)(bn + lr)*K + c0*8;

    const int nk = K >> 5;

    #pragma unroll
    for (int p = 0; p < 2; p++){
        const int ko = p << 5;
        cp_async16(&As[p][lr][c0*8     ], Ag + ko);
        cp_async16(&As[p][lr][c0*8 + 16], Ag + ko + 16);
        cp_async16(&Bs[p][lr][c0*8     ], Bg + ko);
        cp_async16(&Bs[p][lr][c0*8 + 16], Bg + ko + 16);
        cp_commit();
    }

    float acc[2][8][4] = {};
    const int g = lane >> 2;
    const int c = lane & 3;

    int cur = 0;
    for (int kt = 0; kt < nk; kt++){
        cp_wait<1>();
        __syncthreads();

        if (kt + 2 < nk){
            int nxt = cur + 2;
            if (nxt >= NSTG) nxt -= NSTG;
            const int ko = (kt+2) << 5;
            cp_async16(&As[nxt][lr][c0*8     ], Ag + ko);
            cp_async16(&As[nxt][lr][c0*8 + 16], Ag + ko + 16);
            cp_async16(&Bs[nxt][lr][c0*8     ], Bg + ko);
            cp_async16(&Bs[nxt][lr][c0*8 + 16], Bg + ko + 16);
            cp_commit();
        }

        #pragma unroll
        for (int kk = 0; kk < 2; kk++){
            const int kb = kk*16 + 2*c;
            uint32_t af[2][4], bf[8][2];
            #pragma unroll
            for (int i = 0; i < 2; i++){
                const int r0 = mB + i*16 + g;
                af[i][0] = *(const uint32_t*)&As[cur][r0    ][kb    ];
                af[i][1] = *(const uint32_t*)&As[cur][r0 + 8][kb    ];
                af[i][2] = *(const uint32_t*)&As[cur][r0    ][kb + 8];
                af[i][3] = *(const uint32_t*)&As[cur][r0 + 8][kb + 8];
            }
            #pragma unroll
            for (int j = 0; j < 8; j++){
                const int n = nB + j*8 + g;
                bf[j][0] = *(const uint32_t*)&Bs[cur][n][kb    ];
                bf[j][1] = *(const uint32_t*)&Bs[cur][n][kb + 8];
            }
            #pragma unroll
            for (int i = 0; i < 2; i++)
                #pragma unroll
                for (int j = 0; j < 8; j++)
                    mma_f16(acc[i][j], af[i][0], af[i][1], af[i][2], af[i][3],
                            bf[j][0], bf[j][1]);
        }
        cur = (cur + 1 == NSTG) ? 0 : cur + 1;
    }

    #pragma unroll
    for (int i = 0; i < 2; i++){
        const int row = bm + mB + i*16 + g;
        #pragma unroll
        for (int j = 0; j < 8; j++){
            const int col = bn + nB + j*8 + c*2;
            float v0 = acc[i][j][0], v1 = acc[i][j][1];
            float v2 = acc[i][j][2], v3 = acc[i][j][3];
            const size_t o0 = (size_t)row*N + col;
            const size_t o1 = (size_t)(row+8)*N + col;
            if (EPI == 0){
                *(__half2*)(Ch + o0) = __floats2half2_rn(v0, v1);
                *(__half2*)(Ch + o1) = __floats2half2_rn(v2, v3);
            } else if (EPI == 1){
                const float b0 = bias[col], b1 = bias[col+1];
                *(float2*)(C + o0) = make_float2(v0 + b0 + res[o0], v1 + b1 + res[o0+1]);
                *(float2*)(C + o1) = make_float2(v2 + b0 + res[o1], v3 + b1 + res[o1+1]);
            } else {
                const float b0 = bias[col], b1 = bias[col+1];
                *(__half2*)(Ch + o0) = __floats2half2_rn(gelu_tanh(v0 + b0), gelu_tanh(v1 + b1));
                *(__half2*)(Ch + o1) = __floats2half2_rn(gelu_tanh(v2 + b0), gelu_tanh(v3 + b1));
            }
        }
    }
}

// ---------------- FAT fp16 GEMM: CTA 128x256, warp 64x64 ----------------
#define TM 128
#define TN 256
template<int EPI>
__global__ __launch_bounds__(256,1) void hgemm_fat(
    const __half* __restrict__ A, const __half* __restrict__ B,
    float* __restrict__ C, __half* __restrict__ Ch, int M, int N, int K,
    const float* __restrict__ bias, const float* __restrict__ res)
{
    extern __shared__ __half smh[];
    __half (*As)[TM][HSTR] = (__half(*)[TM][HSTR])smh;
    __half (*Bs)[TN][HSTR] = (__half(*)[TN][HSTR])(smh + (size_t)NSTG*TM*HSTR);

    const int tid  = threadIdx.x;
    const int lane = tid & 31;
    const int warp = tid >> 5;
    const int wm = warp >> 2;
    const int wn = warp & 3;
    const int mB = wm*64;
    const int nB = wn*64;
    const int bm = blockIdx.y*TM;
    const int bn = blockIdx.x*TN;

    const int lr = tid >> 1;
    const int c0 = (tid & 1);

    const __half* Ag  = A + (size_t)(bm + lr)*K + c0*8;
    const __half* Bg0 = B + (size_t)(bn + lr)*K + c0*8;
    const __half* Bg1 = B + (size_t)(bn + lr + 128)*K + c0*8;

    const int nk = K >> 5;

    #pragma unroll
    for (int p = 0; p < 2; p++){
        const int ko = p << 5;
        cp_async16(&As[p][lr][c0*8     ], Ag + ko);
        cp_async16(&As[p][lr][c0*8 + 16], Ag + ko + 16);
        cp_async16(&Bs[p][lr][c0*8     ], Bg0 + ko);
        cp_async16(&Bs[p][lr][c0*8 + 16], Bg0 + ko + 16);
        cp_async16(&Bs[p][lr + 128][c0*8     ], Bg1 + ko);
        cp_async16(&Bs[p][lr + 128][c0*8 + 16], Bg1 + ko + 16);
        cp_commit();
    }

    float acc[4][8][4] = {};
    const int g = lane >> 2;
    const int c = lane & 3;

    int cur = 0;
    for (int kt = 0; kt < nk; kt++){
        cp_wait<1>();
        __syncthreads();

        if (kt + 2 < nk){
            int nxt = cur + 2;
            if (nxt >= NSTG) nxt -= NSTG;
            const int ko = (kt+2) << 5;
            cp_async16(&As[nxt][lr][c0*8     ], Ag + ko);
            cp_async16(&As[nxt][lr][c0*8 + 16], Ag + ko + 16);
            cp_async16(&Bs[nxt][lr][c0*8     ], Bg0 + ko);
            cp_async16(&Bs[nxt][lr][c0*8 + 16], Bg0 + ko + 16);
            cp_async16(&Bs[nxt][lr + 128][c0*8     ], Bg1 + ko);
            cp_async16(&Bs[nxt][lr + 128][c0*8 + 16], Bg1 + ko + 16);
            cp_commit();
        }

        #pragma unroll
        for (int kk = 0; kk < 2; kk++){
            const int kb = kk*16 + 2*c;
            uint32_t af[4][4], bf[8][2];
            #pragma unroll
            for (int i = 0; i < 4; i++){
                const int r0 = mB + i*16 + g;
                af[i][0] = *(const uint32_t*)&As[cur][r0    ][kb    ];
                af[i][1] = *(const uint32_t*)&As[cur][r0 + 8][kb    ];
                af[i][2] = *(const uint32_t*)&As[cur][r0    ][kb + 8];
                af[i][3] = *(const uint32_t*)&As[cur][r0 + 8][kb + 8];
            }
            #pragma unroll
            for (int j = 0; j < 8; j++){
                const int n = nB + j*8 + g;
                bf[j][0] = *(const uint32_t*)&Bs[cur][n][kb    ];
                bf[j][1] = *(const uint32_t*)&Bs[cur][n][kb + 8];
            }
            #pragma unroll
            for (int i = 0; i < 4; i++)
                #pragma unroll
                for (int j = 0; j < 8; j++)
                    mma_f16(acc[i][j], af[i][0], af[i][1], af[i][2], af[i][3],
                            bf[j][0], bf[j][1]);
        }
        cur = (cur + 1 == NSTG) ? 0 : cur + 1;
    }

    #pragma unroll
    for (int i = 0; i < 4; i++){
        const int row = bm + mB + i*16 + g;
        #pragma unroll
        for (int j = 0; j < 8; j++){
            const int col = bn + nB + j*8 + c*2;
            float v0 = acc[i][j][0], v1 = acc[i][j][1];
            float v2 = acc[i][j][2], v3 = acc[i][j][3];
            const size_t o0 = (size_t)row*N + col;
            const size_t o1 = (size_t)(row+8)*N + col;
            if (EPI == 0){
                *(__half2*)(Ch + o0) = __floats2half2_rn(v0, v1);
                *(__half2*)(Ch + o1) = __floats2half2_rn(v2, v3);
            } else if (EPI == 1){
                const float b0 = bias[col], b1 = bias[col+1];
                *(float2*)(C + o0) = make_float2(v0 + b0 + res[o0], v1 + b1 + res[o0+1]);
                *(float2*)(C + o1) = make_float2(v2 + b0 + res[o1], v3 + b1 + res[o1+1]);
            } else {
                const float b0 = bias[col], b1 = bias[col+1];
                *(__half2*)(Ch + o0) = __floats2half2_rn(gelu_tanh(v0 + b0), gelu_tanh(v1 + b1));
                *(__half2*)(Ch + o1) = __floats2half2_rn(gelu_tanh(v2 + b0), gelu_tanh(v3 + b1));
            }
        }
    }
}

// ---------------- Causal flash attention, full fp16 mma ----------------
#define HSA 72
#define HSV 68
__global__ __launch_bounds__(128, 4) void attn_h_kernel(const __half* __restrict__ qkv,
                                                        __half* __restrict__ oh)
{
    extern __shared__ __half sh[];
    __half* Qs = sh;
    __half* KP = sh + 64*HSA;
    __half* Vt = sh + 2*64*HSA;

    const int qt = gridDim.x - 1 - blockIdx.x;
    const int bh = blockIdx.y;
    const int b = bh >> 4;
    const int h = bh & 15;
    const int tid = threadIdx.x;
    const int lane = tid & 31;
    const int warp = tid >> 5;
    const int mB = warp * 16;
    const int g = lane >> 2;
    const int c = lane & 3;
    const size_t base = (size_t)b * NSEQ * (3*DD);
    const int hoff = h * HS;

    for (int i = tid; i < 512; i += 128){
        const int row = i >> 3, ch = i & 7;
        *(uint4*)&Qs[row*HSA + ch*8] =
            *(const uint4*)(qkv + base + (size_t)(qt*64+row)*(3*DD) + hoff + ch*8);
    }
    __syncthreads();

    uint32_t qa[4][4];
    #pragma unroll
    for (int kk = 0; kk < 4; kk++){
        qa[kk][0] = *(const uint32_t*)&Qs[(mB+g  )*HSA + kk*16 + 2*c    ];
        qa[kk][1] = *(const uint32_t*)&Qs[(mB+g+8)*HSA + kk*16 + 2*c    ];
        qa[kk][2] = *(const uint32_t*)&Qs[(mB+g  )*HSA + kk*16 + 2*c + 8];
        qa[kk][3] = *(const uint32_t*)&Qs[(mB+g+8)*HSA + kk*16 + 2*c + 8];
    }

    float o[8][4] = {};
    float m0=-1e30f, m1=-1e30f, l0=0.f, l1=0.f;

    const int r0g = qt*64 + mB + g;
    const int r1g = r0g + 8;

    for (int jt = 0; jt <= qt; jt++){
        __syncthreads();
        for (int i = tid; i < 512; i += 128){
            const int row = i >> 3, ch = i & 7;
            const size_t roff = base + (size_t)(jt*64+row)*(3*DD) + hoff + ch*8;
            *(uint4*)&KP[row*HSA + ch*8] = *(const uint4*)(qkv + roff + DD);
            uint4 vv = *(const uint4*)(qkv + roff + 2*DD);
            const __half* vh = (const __half*)&vv;
            #pragma unroll
            for (int d = 0; d < 8; d++)
                Vt[(ch*8 + d)*HSV + row] = vh[d];
        }
        __syncthreads();

        float s[8][4] = {};
        #pragma unroll
        for (int kk = 0; kk < 4; kk++){
            #pragma unroll
            for (int j = 0; j < 8; j++){
                const uint32_t b0 = *(const uint32_t*)&KP[(j*8+g)*HSA + kk*16 + 2*c    ];
                const uint32_t b1 = *(const uint32_t*)&KP[(j*8+g)*HSA + kk*16 + 2*c + 8];
                mma_f16(s[j], qa[kk][0], qa[kk][1], qa[kk][2], qa[kk][3], b0, b1);
            }
        }
        __syncthreads();

        float rm0 = -1e30f, rm1 = -1e30f;
        #pragma unroll
        for (int j = 0; j < 8; j++){
            const int col = jt*64 + j*8 + 2*c;
            #pragma unroll
            for (int t2 = 0; t2 < 2; t2++){
                float v0 = s[j][t2]*0.125f;
                float v1 = s[j][2+t2]*0.125f;
                if (jt == qt){
                    if (col+t2 > r0g) v0 = -1e30f;
                    if (col+t2 > r1g) v1 = -1e30f;
                }
                s[j][t2] = v0;  s[j][2+t2] = v1;
                rm0 = fmaxf(rm0, v0); rm1 = fmaxf(rm1, v1);
            }
        }
        #pragma unroll
        for (int off = 1; off <= 2; off <<= 1){
            rm0 = fmaxf(rm0, __shfl_xor_sync(0xffffffffu, rm0, off));
            rm1 = fmaxf(rm1, __shfl_xor_sync(0xffffffffu, rm1, off));
        }
        const float mn0 = fmaxf(m0, rm0), mn1 = fmaxf(m1, rm1);
        const float alpha0 = __expf(m0 - mn0), alpha1 = __expf(m1 - mn1);
        m0 = mn0; m1 = mn1;

        float rs0 = 0.f, rs1 = 0.f;
        #pragma unroll
        for (int j = 0; j < 8; j++){
            float p0 = __expf(s[j][0] - mn0);
            float p1 = __expf(s[j][1] - mn0);
            float p2 = __expf(s[j][2] - mn1);
            float p3 = __expf(s[j][3] - mn1);
            rs0 += p0 + p1;  rs1 += p2 + p3;
            *(__half2*)&KP[(mB+g  )*HSA + j*8 + 2*c] = __floats2half2_rn(p0, p1);
            *(__half2*)&KP[(mB+g+8)*HSA + j*8 + 2*c] = __floats2half2_rn(p2, p3);
        }
        #pragma unroll
        for (int off = 1; off <= 2; off <<= 1){
            rs0 += __shfl_xor_sync(0xffffffffu, rs0, off);
            rs1 += __shfl_xor_sync(0xffffffffu, rs1, off);
        }
        l0 = l0*alpha0 + rs0;
        l1 = l1*alpha1 + rs1;

        #pragma unroll
        for (int j = 0; j < 8; j++){
            o[j][0] *= alpha0; o[j][1] *= alpha0;
            o[j][2] *= alpha1; o[j][3] *= alpha1;
        }
        __syncwarp();

        #pragma unroll
        for (int kk = 0; kk < 4; kk++){
            const uint32_t a0 = *(const uint32_t*)&KP[(mB+g  )*HSA + kk*16 + 2*c    ];
            const uint32_t a1 = *(const uint32_t*)&KP[(mB+g+8)*HSA + kk*16 + 2*c    ];
            const uint32_t a2 = *(const uint32_t*)&KP[(mB+g  )*HSA + kk*16 + 2*c + 8];
            const uint32_t a3 = *(const uint32_t*)&KP[(mB+g+8)*HSA + kk*16 + 2*c + 8];
            #pragma unroll
            for (int j = 0; j < 8; j++){
                const uint32_t b0 = *(const uint32_t*)&Vt[(j*8+g)*HSV + kk*16 + 2*c    ];
                const uint32_t b1 = *(const uint32_t*)&Vt[(j*8+g)*HSV + kk*16 + 2*c + 8];
                mma_f16(o[j], a0, a1, a2, a3, b0, b1);
            }
        }
    }

    const float inv0 = 1.0f/l0, inv1 = 1.0f/l1;
    #pragma unroll
    for (int j = 0; j < 8; j++){
        const int col = hoff + j*8 + 2*c;
        *(__half2*)(oh + (size_t)(b*NSEQ + r0g)*DD + col) =
            __floats2half2_rn(o[j][0]*inv0, o[j][1]*inv0);
        *(__half2*)(oh + (size_t)(b*NSEQ + r1g)*DD + col) =
            __floats2half2_rn(o[j][2]*inv1, o[j][3]*inv1);
    }
}

// ---------------- launch ----------------
extern "C" void kernel_launch(void* const* d_in, const int* in_sizes, int n_in,
                              void* d_out, int out_size)
{
    const float* x    = (const float*)d_in[0];
    const float* ln1s = (const float*)d_in[1];
    const float* ln1b = (const float*)d_in[2];
    const float* wqkv = (const float*)d_in[3];
    const float* wout = (const float*)d_in[4];
    const float* bout = (const float*)d_in[5];
    const float* ln2s = (const float*)d_in[6];
    const float* ln2b = (const float*)d_in[7];
    const float* w1   = (const float*)d_in[8];
    const float* b1   = (const float*)d_in[9];
    const float* w2   = (const float*)d_in[10];
    const float* b2   = (const float*)d_in[11];
    float* out = (float*)d_out;

    float *p_x1;
    __half *p_xn, *p_qkv, *p_oh, *p_xn2, *p_y;
    __half *p_wqkvh, *p_wouth, *p_w1h, *p_w2h;
    cudaGetSymbolAddress((void**)&p_xn , g_xn );
    cudaGetSymbolAddress((void**)&p_qkv, g_qkv);
    cudaGetSymbolAddress((void**)&p_oh , g_oh );
    cudaGetSymbolAddress((void**)&p_x1 , g_x1 );
    cudaGetSymbolAddress((void**)&p_xn2, g_xn2);
    cudaGetSymbolAddress((void**)&p_y  , g_y  );
    cudaGetSymbolAddress((void**)&p_wqkvh, g_wqkvh);
    cudaGetSymbolAddress((void**)&p_wouth, g_wouth);
    cudaGetSymbolAddress((void**)&p_w1h  , g_w1h  );
    cudaGetSymbolAddress((void**)&p_w2h  , g_w2h  );

    const int attn_smem = (2*64*HSA + 64*HSV)*sizeof(__half);     // 27136 B
    cudaFuncSetAttribute(attn_h_kernel, cudaFuncAttributeMaxDynamicSharedMemorySize, attn_smem);
    const int thin_smem = 2*NSTG*128*HSTR*sizeof(__half);         // 61440 B
    cudaFuncSetAttribute(hgemm_thin<1>, cudaFuncAttributeMaxDynamicSharedMemorySize, thin_smem);
    const int fat_smem = NSTG*(TM + TN)*HSTR*sizeof(__half);      // 92160 B
    cudaFuncSetAttribute(hgemm_fat<0>, cudaFuncAttributeMaxDynamicSharedMemorySize, fat_smem);
    cudaFuncSetAttribute(hgemm_fat<2>, cudaFuncAttributeMaxDynamicSharedMemorySize, fat_smem);

    // weight prep: single merged launch (8192 blocks)
    wtrans_all_kernel<<<8192,256>>>(wqkv, p_wqkvh, wout, p_wouth, w1, p_w1h, w2, p_w2h);

    // LN1 -> fp16
    ln_kernel<<<MM,256>>>(x, ln1s, ln1b, p_xn);
    // QKV (fat: grid 12x32=384) -> fp16
    hgemm_fat<0><<<dim3(3*DD/TN, MM/TM),256,fat_smem>>>(p_xn, p_wqkvh, nullptr, p_qkv,
                                                        MM, 3*DD, DD, nullptr, nullptr);
    // causal attention (fp16) -> fp16
    attn_h_kernel<<<dim3(NSEQ/64, BB*NH),128,attn_smem>>>(p_qkv, p_oh);
    // out-proj + residual (thin: grid 8x32=256, 2 CTA/SM) -> fp32
    hgemm_thin<1><<<dim3(DD/128, MM/128),256,thin_smem>>>(p_oh, p_wouth, p_x1, nullptr,
                                                          MM, DD, DD, bout, x);
    // LN2 -> fp16
    ln_kernel<<<MM,256>>>(p_x1, ln2s, ln2b, p_xn2);
    // MLP up + GELU (fat: grid 8x32=256) -> fp16
    hgemm_fat<2><<<dim3(2*DD/TN, MM/TM),256,fat_smem>>>(p_xn2, p_w1h, nullptr, p_y,
                                                        MM, 2*DD, DD, b1, nullptr);
    // MLP down + residual (thin: grid 8x32=256, K=2048) -> out fp32
    hgemm_thin<1><<<dim3(DD/128, MM/128),256,thin_smem>>>(p_y, p_w2h, out, nullptr,
                                                          MM, DD, 2*DD, b2, p_x1);
}

// round 16
// speedup vs baseline: 1.0251x; 1.0251x over previous
#include <cuda_runtime.h>
#include <cuda_fp16.h>
#include <math.h>
#include <stdint.h>

#define BB 2
#define NSEQ 2048
#define DD 1024
#define NH 16
#define HS 64
#define MM (BB*NSEQ)   // 4096 rows

// ---------------- scratch (allocation-free, __device__ globals) ----------------
__device__ __align__(16) __half g_xn [(size_t)MM*DD];
__device__ __align__(16) __half g_qkv[(size_t)MM*3*DD];
__device__ __align__(16) __half g_oh [(size_t)MM*DD];
__device__ float g_x1 [(size_t)MM*DD];
__device__ __align__(16) __half g_xn2[(size_t)MM*DD];
__device__ __align__(16) __half g_y  [(size_t)MM*2*DD];
__device__ __align__(16) __half g_wqkvh[(size_t)3*DD*DD];
__device__ __align__(16) __half g_wouth[(size_t)DD*DD];
__device__ __align__(16) __half g_w1h  [(size_t)2*DD*DD];
__device__ __align__(16) __half g_w2h  [(size_t)DD*2*DD];

__device__ __forceinline__ float gelu_tanh(float x){
    float u = 0.7978845608028654f * (x + 0.044715f*x*x*x);
    float t = 1.0f - 2.0f/(__expf(2.0f*u)+1.0f);
    return 0.5f*x*(1.0f+t);
}

__device__ __forceinline__ void cp_async16(void* smem, const void* gmem){
    unsigned s = (unsigned)__cvta_generic_to_shared(smem);
    asm volatile("cp.async.cg.shared.global [%0], [%1], 16;" :: "r"(s), "l"(gmem));
}
__device__ __forceinline__ void cp_commit(){ asm volatile("cp.async.commit_group;"); }
template<int N> __device__ __forceinline__ void cp_wait(){ asm volatile("cp.async.wait_group %0;" :: "n"(N)); }

__device__ __forceinline__ void mma_f16(float c[4], uint32_t a0, uint32_t a1,
                                        uint32_t a2, uint32_t a3,
                                        uint32_t b0, uint32_t b1){
    asm volatile(
        "mma.sync.aligned.m16n8k16.row.col.f32.f16.f16.f32 "
        "{%0,%1,%2,%3},{%4,%5,%6,%7},{%8,%9},{%0,%1,%2,%3};"
        : "+f"(c[0]), "+f"(c[1]), "+f"(c[2]), "+f"(c[3])
        : "r"(a0), "r"(a1), "r"(a2), "r"(a3), "r"(b0), "r"(b1));
}

// ---------------- merged weight prep: 4 transposes, one launch ----------------
__global__ __launch_bounds__(256) void wtrans_all_kernel(
    const float* __restrict__ W0, __half* __restrict__ O0,
    const float* __restrict__ W1, __half* __restrict__ O1,
    const float* __restrict__ W2, __half* __restrict__ O2,
    const float* __restrict__ W3, __half* __restrict__ O3)
{
    __shared__ float tile[32][33];
    int blk = blockIdx.x;
    const float* W; __half* O; int K, N, nbx;
    if (blk < 3072)      { W=W0; O=O0; K=DD;   N=3*DD; nbx=96; }
    else if (blk < 4096) { W=W1; O=O1; K=DD;   N=DD;   nbx=32; blk -= 3072; }
    else if (blk < 6144) { W=W2; O=O2; K=DD;   N=2*DD; nbx=64; blk -= 4096; }
    else                 { W=W3; O=O3; K=2*DD; N=DD;   nbx=32; blk -= 6144; }
    const int n0 = (blk % nbx)*32;
    const int k0 = (blk / nbx)*32;
    const int tx = threadIdx.x & 31, ty = threadIdx.x >> 5;
    for (int r = ty; r < 32; r += 8)
        tile[r][tx] = W[(size_t)(k0+r)*N + n0 + tx];
    __syncthreads();
    for (int r = ty; r < 32; r += 8)
        O[(size_t)(n0+r)*K + k0 + tx] = __float2half_rn(tile[tx][r]);
}

// ---------------- LayerNorm -> fp16 ----------------
__global__ __launch_bounds__(256) void ln_kernel(const float* __restrict__ x,
        const float* __restrict__ sc, const float* __restrict__ bi,
        __half* __restrict__ out)
{
    const int row = blockIdx.x;
    const int t = threadIdx.x;
    const float4 v = ((const float4*)(x + (size_t)row*DD))[t];
    float s  = v.x+v.y+v.z+v.w;
    float sq = v.x*v.x+v.y*v.y+v.z*v.z+v.w*v.w;
    #pragma unroll
    for (int o=16;o>0;o>>=1){
        s  += __shfl_xor_sync(0xffffffffu,s ,o);
        sq += __shfl_xor_sync(0xffffffffu,sq,o);
    }
    __shared__ float ss[8], sqs[8];
    const int warp=t>>5, lane=t&31;
    if (lane==0){ ss[warp]=s; sqs[warp]=sq; }
    __syncthreads();
    if (t==0){
        float a=0.f,b=0.f;
        #pragma unroll
        for(int i=0;i<8;i++){a+=ss[i]; b+=sqs[i];}
        ss[0]=a; sqs[0]=b;
    }
    __syncthreads();
    const float mean = ss[0]*(1.0f/DD);
    const float var  = sqs[0]*(1.0f/DD) - mean*mean;
    const float inv  = rsqrtf(var + 1e-6f);
    const float4 sc4 = ((const float4*)sc)[t];
    const float4 bi4 = ((const float4*)bi)[t];
    __half2* p = (__half2*)(out + (size_t)row*DD + 4*t);
    p[0] = __floats2half2_rn((v.x-mean)*inv*sc4.x + bi4.x,
                             (v.y-mean)*inv*sc4.y + bi4.y);
    p[1] = __floats2half2_rn((v.z-mean)*inv*sc4.z + bi4.z,
                             (v.w-mean)*inv*sc4.w + bi4.w);
}

// ---------------- FAT fp16 GEMM: CTA 128x256, warp 64x64, 3-stage ----------------
#define HSTR 40
#define NSTG 3
#define TM 128
#define TN 256
template<int EPI>
__global__ __launch_bounds__(256,1) void hgemm_fat(
    const __half* __restrict__ A, const __half* __restrict__ B,
    float* __restrict__ C, __half* __restrict__ Ch, int M, int N, int K,
    const float* __restrict__ bias, const float* __restrict__ res)
{
    extern __shared__ __half smh[];
    __half (*As)[TM][HSTR] = (__half(*)[TM][HSTR])smh;
    __half (*Bs)[TN][HSTR] = (__half(*)[TN][HSTR])(smh + (size_t)NSTG*TM*HSTR);

    const int tid  = threadIdx.x;
    const int lane = tid & 31;
    const int warp = tid >> 5;
    const int wm = warp >> 2;
    const int wn = warp & 3;
    const int mB = wm*64;
    const int nB = wn*64;
    const int bm = blockIdx.y*TM;
    const int bn = blockIdx.x*TN;

    const int lr = tid >> 1;
    const int c0 = (tid & 1);

    const __half* Ag  = A + (size_t)(bm + lr)*K + c0*8;
    const __half* Bg0 = B + (size_t)(bn + lr)*K + c0*8;
    const __half* Bg1 = B + (size_t)(bn + lr + 128)*K + c0*8;

    const int nk = K >> 5;

    #pragma unroll
    for (int p = 0; p < 2; p++){
        const int ko = p << 5;
        cp_async16(&As[p][lr][c0*8     ], Ag + ko);
        cp_async16(&As[p][lr][c0*8 + 16], Ag + ko + 16);
        cp_async16(&Bs[p][lr][c0*8     ], Bg0 + ko);
        cp_async16(&Bs[p][lr][c0*8 + 16], Bg0 + ko + 16);
        cp_async16(&Bs[p][lr + 128][c0*8     ], Bg1 + ko);
        cp_async16(&Bs[p][lr + 128][c0*8 + 16], Bg1 + ko + 16);
        cp_commit();
    }

    float acc[4][8][4] = {};
    const int g = lane >> 2;
    const int c = lane & 3;

    int cur = 0;
    for (int kt = 0; kt < nk; kt++){
        cp_wait<1>();
        __syncthreads();

        if (kt + 2 < nk){
            int nxt = cur + 2;
            if (nxt >= NSTG) nxt -= NSTG;
            const int ko = (kt+2) << 5;
            cp_async16(&As[nxt][lr][c0*8     ], Ag + ko);
            cp_async16(&As[nxt][lr][c0*8 + 16], Ag + ko + 16);
            cp_async16(&Bs[nxt][lr][c0*8     ], Bg0 + ko);
            cp_async16(&Bs[nxt][lr][c0*8 + 16], Bg0 + ko + 16);
            cp_async16(&Bs[nxt][lr + 128][c0*8     ], Bg1 + ko);
            cp_async16(&Bs[nxt][lr + 128][c0*8 + 16], Bg1 + ko + 16);
            cp_commit();
        }

        #pragma unroll
        for (int kk = 0; kk < 2; kk++){
            const int kb = kk*16 + 2*c;
            uint32_t af[4][4], bf[8][2];
            #pragma unroll
            for (int i = 0; i < 4; i++){
                const int r0 = mB + i*16 + g;
                af[i][0] = *(const uint32_t*)&As[cur][r0    ][kb    ];
                af[i][1] = *(const uint32_t*)&As[cur][r0 + 8][kb    ];
                af[i][2] = *(const uint32_t*)&As[cur][r0    ][kb + 8];
                af[i][3] = *(const uint32_t*)&As[cur][r0 + 8][kb + 8];
            }
            #pragma unroll
            for (int j = 0; j < 8; j++){
                const int n = nB + j*8 + g;
                bf[j][0] = *(const uint32_t*)&Bs[cur][n][kb    ];
                bf[j][1] = *(const uint32_t*)&Bs[cur][n][kb + 8];
            }
            #pragma unroll
            for (int i = 0; i < 4; i++)
                #pragma unroll
                for (int j = 0; j < 8; j++)
                    mma_f16(acc[i][j], af[i][0], af[i][1], af[i][2], af[i][3],
                            bf[j][0], bf[j][1]);
        }
        cur = (cur + 1 == NSTG) ? 0 : cur + 1;
    }

    #pragma unroll
    for (int i = 0; i < 4; i++){
        const int row = bm + mB + i*16 + g;
        #pragma unroll
        for (int j = 0; j < 8; j++){
            const int col = bn + nB + j*8 + c*2;
            float v0 = acc[i][j][0], v1 = acc[i][j][1];
            float v2 = acc[i][j][2], v3 = acc[i][j][3];
            const size_t o0 = (size_t)row*N + col;
            const size_t o1 = (size_t)(row+8)*N + col;
            if (EPI == 0){
                *(__half2*)(Ch + o0) = __floats2half2_rn(v0, v1);
                *(__half2*)(Ch + o1) = __floats2half2_rn(v2, v3);
            } else if (EPI == 1){
                const float b0 = bias[col], b1 = bias[col+1];
                *(float2*)(C + o0) = make_float2(v0 + b0 + res[o0], v1 + b1 + res[o0+1]);
                *(float2*)(C + o1) = make_float2(v2 + b0 + res[o1], v3 + b1 + res[o1+1]);
            } else {
                const float b0 = bias[col], b1 = bias[col+1];
                *(__half2*)(Ch + o0) = __floats2half2_rn(gelu_tanh(v0 + b0), gelu_tanh(v1 + b1));
                *(__half2*)(Ch + o1) = __floats2half2_rn(gelu_tanh(v2 + b0), gelu_tanh(v3 + b1));
            }
        }
    }
}

// ---------------- Causal flash attention: BM=128, 256 threads, fp16 mma ----------------
// Qs[128][72] holds Q, then (after fragment hoist) is reused as P[128 rows][64 keys].
// Ks[64][72] holds K tile. Vt[64][68] holds V^T.
#define HSA 72
#define HSV 68
__global__ __launch_bounds__(256, 2) void attn_h_kernel(const __half* __restrict__ qkv,
                                                        __half* __restrict__ oh)
{
    extern __shared__ __half sh[];
    __half* QP = sh;                   // [128][HSA]  Q then P
    __half* Ks = sh + 128*HSA;         // [64][HSA]
    __half* Vt = sh + 128*HSA + 64*HSA;// [64][HSV]

    const int qtile = gridDim.x - 1 - blockIdx.x;   // heavy tiles first
    const int bh = blockIdx.y;
    const int b = bh >> 4;
    const int h = bh & 15;
    const int tid = threadIdx.x;
    const int lane = tid & 31;
    const int warp = tid >> 5;
    const int mB = warp * 16;          // warp owns rows mB..mB+15 of the 128-row tile
    const int g = lane >> 2;
    const int c = lane & 3;
    const size_t base = (size_t)b * NSEQ * (3*DD);
    const int hoff = h * HS;
    const int qt0 = qtile * 128;       // first global query row

    // load Q tile: 128 rows x 64 halves
    for (int i = tid; i < 1024; i += 256){
        const int row = i >> 3, ch = i & 7;
        *(uint4*)&QP[row*HSA + ch*8] =
            *(const uint4*)(qkv + base + (size_t)(qt0+row)*(3*DD) + hoff + ch*8);
    }
    __syncthreads();

    // hoist Q fragments; afterwards QP is reused for P
    uint32_t qa[4][4];
    #pragma unroll
    for (int kk = 0; kk < 4; kk++){
        qa[kk][0] = *(const uint32_t*)&QP[(mB+g  )*HSA + kk*16 + 2*c    ];
        qa[kk][1] = *(const uint32_t*)&QP[(mB+g+8)*HSA + kk*16 + 2*c    ];
        qa[kk][2] = *(const uint32_t*)&QP[(mB+g  )*HSA + kk*16 + 2*c + 8];
        qa[kk][3] = *(const uint32_t*)&QP[(mB+g+8)*HSA + kk*16 + 2*c + 8];
    }
    __syncthreads();   // Q reads complete before any P writes

    float o[8][4] = {};
    float m0=-1e30f, m1=-1e30f, l0=0.f, l1=0.f;

    const int r0g = qt0 + mB + g;
    const int r1g = r0g + 8;
    const int njt = 2*qtile + 2;       // KV tiles 0 .. 2*qtile+1

    for (int jt = 0; jt < njt; jt++){
        __syncthreads();   // prior QK^T reads of Ks and PV reads of Vt complete
        for (int i = tid; i < 512; i += 256){
            const int row = i >> 3, ch = i & 7;
            const size_t roff = base + (size_t)(jt*64+row)*(3*DD) + hoff + ch*8;
            *(uint4*)&Ks[row*HSA + ch*8] = *(const uint4*)(qkv + roff + DD);
            uint4 vv = *(const uint4*)(qkv + roff + 2*DD);
            const __half* vh = (const __half*)&vv;
            #pragma unroll
            for (int d = 0; d < 8; d++)
                Vt[(ch*8 + d)*HSV + row] = vh[d];
        }
        __syncthreads();

        // S = Q K^T
        float s[8][4] = {};
        #pragma unroll
        for (int kk = 0; kk < 4; kk++){
            #pragma unroll
            for (int j = 0; j < 8; j++){
                const uint32_t b0 = *(const uint32_t*)&Ks[(j*8+g)*HSA + kk*16 + 2*c    ];
                const uint32_t b1 = *(const uint32_t*)&Ks[(j*8+g)*HSA + kk*16 + 2*c + 8];
                mma_f16(s[j], qa[kk][0], qa[kk][1], qa[kk][2], qa[kk][3], b0, b1);
            }
        }

        // scale + causal mask + row max
        const bool maskTile = (jt >= 2*qtile);   // only last two tiles cross diagonal
        float rm0 = -1e30f, rm1 = -1e30f;
        #pragma unroll
        for (int j = 0; j < 8; j++){
            const int col = jt*64 + j*8 + 2*c;
            #pragma unroll
            for (int t2 = 0; t2 < 2; t2++){
                float v0 = s[j][t2]*0.125f;
                float v1 = s[j][2+t2]*0.125f;
                if (maskTile){
                    if (col+t2 > r0g) v0 = -1e30f;
                    if (col+t2 > r1g) v1 = -1e30f;
                }
                s[j][t2] = v0;  s[j][2+t2] = v1;
                rm0 = fmaxf(rm0, v0); rm1 = fmaxf(rm1, v1);
            }
        }
        #pragma unroll
        for (int off = 1; off <= 2; off <<= 1){
            rm0 = fmaxf(rm0, __shfl_xor_sync(0xffffffffu, rm0, off));
            rm1 = fmaxf(rm1, __shfl_xor_sync(0xffffffffu, rm1, off));
        }
        const float mn0 = fmaxf(m0, rm0), mn1 = fmaxf(m1, rm1);
        const float alpha0 = __expf(m0 - mn0), alpha1 = __expf(m1 - mn1);
        m0 = mn0; m1 = mn1;

        float rs0 = 0.f, rs1 = 0.f;
        #pragma unroll
        for (int j = 0; j < 8; j++){
            float p0 = __expf(s[j][0] - mn0);
            float p1 = __expf(s[j][1] - mn0);
            float p2 = __expf(s[j][2] - mn1);
            float p3 = __expf(s[j][3] - mn1);
            rs0 += p0 + p1;  rs1 += p2 + p3;
            *(__half2*)&QP[(mB+g  )*HSA + j*8 + 2*c] = __floats2half2_rn(p0, p1);
            *(__half2*)&QP[(mB+g+8)*HSA + j*8 + 2*c] = __floats2half2_rn(p2, p3);
        }
        #pragma unroll
        for (int off = 1; off <= 2; off <<= 1){
            rs0 += __shfl_xor_sync(0xffffffffu, rs0, off);
            rs1 += __shfl_xor_sync(0xffffffffu, rs1, off);
        }
        l0 = l0*alpha0 + rs0;
        l1 = l1*alpha1 + rs1;

        #pragma unroll
        for (int j = 0; j < 8; j++){
            o[j][0] *= alpha0; o[j][1] *= alpha0;
            o[j][2] *= alpha1; o[j][3] *= alpha1;
        }
        __syncwarp();      // P rows are warp-private

        // O += P @ V
        #pragma unroll
        for (int kk = 0; kk < 4; kk++){
            const uint32_t a0 = *(const uint32_t*)&QP[(mB+g  )*HSA + kk*16 + 2*c    ];
            const uint32_t a1 = *(const uint32_t*)&QP[(mB+g+8)*HSA + kk*16 + 2*c    ];
            const uint32_t a2 = *(const uint32_t*)&QP[(mB+g  )*HSA + kk*16 + 2*c + 8];
            const uint32_t a3 = *(const uint32_t*)&QP[(mB+g+8)*HSA + kk*16 + 2*c + 8];
            #pragma unroll
            for (int j = 0; j < 8; j++){
                const uint32_t b0 = *(const uint32_t*)&Vt[(j*8+g)*HSV + kk*16 + 2*c    ];
                const uint32_t b1 = *(const uint32_t*)&Vt[(j*8+g)*HSV + kk*16 + 2*c + 8];
                mma_f16(o[j], a0, a1, a2, a3, b0, b1);
            }
        }
    }

    const float inv0 = 1.0f/l0, inv1 = 1.0f/l1;
    #pragma unroll
    for (int j = 0; j < 8; j++){
        const int col = hoff + j*8 + 2*c;
        *(__half2*)(oh + (size_t)(b*NSEQ + r0g)*DD + col) =
            __floats2half2_rn(o[j][0]*inv0, o[j][1]*inv0);
        *(__half2*)(oh + (size_t)(b*NSEQ + r1g)*DD + col) =
            __floats2half2_rn(o[j][2]*inv1, o[j][3]*inv1);
    }
}

// ---------------- launch ----------------
extern "C" void kernel_launch(void* const* d_in, const int* in_sizes, int n_in,
                              void* d_out, int out_size)
{
    const float* x    = (const float*)d_in[0];
    const float* ln1s = (const float*)d_in[1];
    const float* ln1b = (const float*)d_in[2];
    const float* wqkv = (const float*)d_in[3];
    const float* wout = (const float*)d_in[4];
    const float* bout = (const float*)d_in[5];
    const float* ln2s = (const float*)d_in[6];
    const float* ln2b = (const float*)d_in[7];
    const float* w1   = (const float*)d_in[8];
    const float* b1   = (const float*)d_in[9];
    const float* w2   = (const float*)d_in[10];
    const float* b2   = (const float*)d_in[11];
    float* out = (float*)d_out;

    float *p_x1;
    __half *p_xn, *p_qkv, *p_oh, *p_xn2, *p_y;
    __half *p_wqkvh, *p_wouth, *p_w1h, *p_w2h;
    cudaGetSymbolAddress((void**)&p_xn , g_xn );
    cudaGetSymbolAddress((void**)&p_qkv, g_qkv);
    cudaGetSymbolAddress((void**)&p_oh , g_oh );
    cudaGetSymbolAddress((void**)&p_x1 , g_x1 );
    cudaGetSymbolAddress((void**)&p_xn2, g_xn2);
    cudaGetSymbolAddress((void**)&p_y  , g_y  );
    cudaGetSymbolAddress((void**)&p_wqkvh, g_wqkvh);
    cudaGetSymbolAddress((void**)&p_wouth, g_wouth);
    cudaGetSymbolAddress((void**)&p_w1h  , g_w1h  );
    cudaGetSymbolAddress((void**)&p_w2h  , g_w2h  );

    const int attn_smem = (128*HSA + 64*HSA + 64*HSV)*sizeof(__half);   // 36352 B
    cudaFuncSetAttribute(attn_h_kernel, cudaFuncAttributeMaxDynamicSharedMemorySize, attn_smem);
    const int fat_smem = NSTG*(TM + TN)*HSTR*sizeof(__half);            // 92160 B
    cudaFuncSetAttribute(hgemm_fat<0>, cudaFuncAttributeMaxDynamicSharedMemorySize, fat_smem);
    cudaFuncSetAttribute(hgemm_fat<1>, cudaFuncAttributeMaxDynamicSharedMemorySize, fat_smem);
    cudaFuncSetAttribute(hgemm_fat<2>, cudaFuncAttributeMaxDynamicSharedMemorySize, fat_smem);

    // weight prep: single merged launch
    wtrans_all_kernel<<<8192,256>>>(wqkv, p_wqkvh, wout, p_wouth, w1, p_w1h, w2, p_w2h);

    // LN1 -> fp16
    ln_kernel<<<MM,256>>>(x, ln1s, ln1b, p_xn);
    // QKV
    hgemm_fat<0><<<dim3(3*DD/TN, MM/TM),256,fat_smem>>>(p_xn, p_wqkvh, nullptr, p_qkv,
                                                        MM, 3*DD, DD, nullptr, nullptr);
    // causal attention: 128-row query tiles
    attn_h_kernel<<<dim3(NSEQ/128, BB*NH),256,attn_smem>>>(p_qkv, p_oh);
    // out-proj + residual
    hgemm_fat<1><<<dim3(DD/TN, MM/TM),256,fat_smem>>>(p_oh, p_wouth, p_x1, nullptr,
                                                      MM, DD, DD, bout, x);
    // LN2 -> fp16
    ln_kernel<<<MM,256>>>(p_x1, ln2s, ln2b, p_xn2);
    // MLP up + GELU
    hgemm_fat<2><<<dim3(2*DD/TN, MM/TM),256,fat_smem>>>(p_xn2, p_w1h, nullptr, p_y,
                                                        MM, 2*DD, DD, b1, nullptr);
    // MLP down + residual
    hgemm_fat<1><<<dim3(DD/TN, MM/TM),256,fat_smem>>>(p_y, p_w2h, out, nullptr,
                                                      MM, DD, 2*DD, b2, p_x1);
}

// round 17
// speedup vs baseline: 1.1027x; 1.0757x over previous
#include <cuda_runtime.h>
#include <cuda_fp16.h>
#include <math.h>
#include <stdint.h>

#define BB 2
#define NSEQ 2048
#define DD 1024
#define NH 16
#define HS 64
#define MM (BB*NSEQ)   // 4096 rows

// ---------------- scratch (allocation-free, __device__ globals) ----------------
__device__ __align__(16) __half g_xn [(size_t)MM*DD];
__device__ __align__(16) __half g_qkv[(size_t)MM*3*DD];
__device__ __align__(16) __half g_oh [(size_t)MM*DD];
__device__ float g_x1 [(size_t)MM*DD];
__device__ __align__(16) __half g_xn2[(size_t)MM*DD];
__device__ __align__(16) __half g_y  [(size_t)MM*2*DD];
__device__ __align__(16) __half g_wqkvh[(size_t)3*DD*DD];
__device__ __align__(16) __half g_wouth[(size_t)DD*DD];
__device__ __align__(16) __half g_w1h  [(size_t)2*DD*DD];
__device__ __align__(16) __half g_w2h  [(size_t)DD*2*DD];

__device__ __forceinline__ float gelu_tanh(float x){
    float u = 0.7978845608028654f * (x + 0.044715f*x*x*x);
    float t = 1.0f - 2.0f/(__expf(2.0f*u)+1.0f);
    return 0.5f*x*(1.0f+t);
}

__device__ __forceinline__ void cp_async16(void* smem, const void* gmem){
    unsigned s = (unsigned)__cvta_generic_to_shared(smem);
    asm volatile("cp.async.cg.shared.global [%0], [%1], 16;" :: "r"(s), "l"(gmem));
}
__device__ __forceinline__ void cp_commit(){ asm volatile("cp.async.commit_group;"); }
template<int N> __device__ __forceinline__ void cp_wait(){ asm volatile("cp.async.wait_group %0;" :: "n"(N)); }

__device__ __forceinline__ uint32_t s2u(const void* p){
    return (uint32_t)__cvta_generic_to_shared(p);
}

__device__ __forceinline__ void mma_f16(float c[4], uint32_t a0, uint32_t a1,
                                        uint32_t a2, uint32_t a3,
                                        uint32_t b0, uint32_t b1){
    asm volatile(
        "mma.sync.aligned.m16n8k16.row.col.f32.f16.f16.f32 "
        "{%0,%1,%2,%3},{%4,%5,%6,%7},{%8,%9},{%0,%1,%2,%3};"
        : "+f"(c[0]), "+f"(c[1]), "+f"(c[2]), "+f"(c[3])
        : "r"(a0), "r"(a1), "r"(a2), "r"(a3), "r"(b0), "r"(b1));
}

#define LDSM_X4(r0,r1,r2,r3, addr) \
    asm volatile("ldmatrix.sync.aligned.m8n8.x4.shared.b16 {%0,%1,%2,%3}, [%4];" \
        : "=r"(r0), "=r"(r1), "=r"(r2), "=r"(r3) : "r"(addr))
#define LDSM_X2(r0,r1, addr) \
    asm volatile("ldmatrix.sync.aligned.m8n8.x2.shared.b16 {%0,%1}, [%2];" \
        : "=r"(r0), "=r"(r1) : "r"(addr))
#define LDSM_X2T(r0,r1, addr) \
    asm volatile("ldmatrix.sync.aligned.m8n8.x2.trans.shared.b16 {%0,%1}, [%2];" \
        : "=r"(r0), "=r"(r1) : "r"(addr))

// ---------------- merged weight prep: 4 transposes, one launch ----------------
__global__ __launch_bounds__(256) void wtrans_all_kernel(
    const float* __restrict__ W0, __half* __restrict__ O0,
    const float* __restrict__ W1, __half* __restrict__ O1,
    const float* __restrict__ W2, __half* __restrict__ O2,
    const float* __restrict__ W3, __half* __restrict__ O3)
{
    __shared__ float tile[32][33];
    int blk = blockIdx.x;
    const float* W; __half* O; int K, N, nbx;
    if (blk < 3072)      { W=W0; O=O0; K=DD;   N=3*DD; nbx=96; }
    else if (blk < 4096) { W=W1; O=O1; K=DD;   N=DD;   nbx=32; blk -= 3072; }
    else if (blk < 6144) { W=W2; O=O2; K=DD;   N=2*DD; nbx=64; blk -= 4096; }
    else                 { W=W3; O=O3; K=2*DD; N=DD;   nbx=32; blk -= 6144; }
    const int n0 = (blk % nbx)*32;
    const int k0 = (blk / nbx)*32;
    const int tx = threadIdx.x & 31, ty = threadIdx.x >> 5;
    for (int r = ty; r < 32; r += 8)
        tile[r][tx] = W[(size_t)(k0+r)*N + n0 + tx];
    __syncthreads();
    for (int r = ty; r < 32; r += 8)
        O[(size_t)(n0+r)*K + k0 + tx] = __float2half_rn(tile[tx][r]);
}

// ---------------- LayerNorm -> fp16 ----------------
__global__ __launch_bounds__(256) void ln_kernel(const float* __restrict__ x,
        const float* __restrict__ sc, const float* __restrict__ bi,
        __half* __restrict__ out)
{
    const int row = blockIdx.x;
    const int t = threadIdx.x;
    const float4 v = ((const float4*)(x + (size_t)row*DD))[t];
    float s  = v.x+v.y+v.z+v.w;
    float sq = v.x*v.x+v.y*v.y+v.z*v.z+v.w*v.w;
    #pragma unroll
    for (int o=16;o>0;o>>=1){
        s  += __shfl_xor_sync(0xffffffffu,s ,o);
        sq += __shfl_xor_sync(0xffffffffu,sq,o);
    }
    __shared__ float ss[8], sqs[8];
    const int warp=t>>5, lane=t&31;
    if (lane==0){ ss[warp]=s; sqs[warp]=sq; }
    __syncthreads();
    if (t==0){
        float a=0.f,b=0.f;
        #pragma unroll
        for(int i=0;i<8;i++){a+=ss[i]; b+=sqs[i];}
        ss[0]=a; sqs[0]=b;
    }
    __syncthreads();
    const float mean = ss[0]*(1.0f/DD);
    const float var  = sqs[0]*(1.0f/DD) - mean*mean;
    const float inv  = rsqrtf(var + 1e-6f);
    const float4 sc4 = ((const float4*)sc)[t];
    const float4 bi4 = ((const float4*)bi)[t];
    __half2* p = (__half2*)(out + (size_t)row*DD + 4*t);
    p[0] = __floats2half2_rn((v.x-mean)*inv*sc4.x + bi4.x,
                             (v.y-mean)*inv*sc4.y + bi4.y);
    p[1] = __floats2half2_rn((v.z-mean)*inv*sc4.z + bi4.z,
                             (v.w-mean)*inv*sc4.w + bi4.w);
}

// ---------------- FAT fp16 GEMM: CTA 128x256, warp 64x64, ldmatrix feed ----------------
#define HSTR 40
#define NSTG 3
#define TM 128
#define TN 256
template<int EPI>
__global__ __launch_bounds__(256,1) void hgemm_fat(
    const __half* __restrict__ A, const __half* __restrict__ B,
    float* __restrict__ C, __half* __restrict__ Ch, int M, int N, int K,
    const float* __restrict__ bias, const float* __restrict__ res)
{
    extern __shared__ __half smh[];
    __half (*As)[TM][HSTR] = (__half(*)[TM][HSTR])smh;
    __half (*Bs)[TN][HSTR] = (__half(*)[TN][HSTR])(smh + (size_t)NSTG*TM*HSTR);

    const int tid  = threadIdx.x;
    const int lane = tid & 31;
    const int warp = tid >> 5;
    const int wm = warp >> 2;
    const int wn = warp & 3;
    const int mB = wm*64;
    const int nB = wn*64;
    const int bm = blockIdx.y*TM;
    const int bn = blockIdx.x*TN;

    const int lr = tid >> 1;
    const int c0 = (tid & 1);

    const __half* Ag  = A + (size_t)(bm + lr)*K + c0*8;
    const __half* Bg0 = B + (size_t)(bn + lr)*K + c0*8;
    const __half* Bg1 = B + (size_t)(bn + lr + 128)*K + c0*8;

    const int nk = K >> 5;

    #pragma unroll
    for (int p = 0; p < 2; p++){
        const int ko = p << 5;
        cp_async16(&As[p][lr][c0*8     ], Ag + ko);
        cp_async16(&As[p][lr][c0*8 + 16], Ag + ko + 16);
        cp_async16(&Bs[p][lr][c0*8     ], Bg0 + ko);
        cp_async16(&Bs[p][lr][c0*8 + 16], Bg0 + ko + 16);
        cp_async16(&Bs[p][lr + 128][c0*8     ], Bg1 + ko);
        cp_async16(&Bs[p][lr + 128][c0*8 + 16], Bg1 + ko + 16);
        cp_commit();
    }

    float acc[4][8][4] = {};
    const int g = lane >> 2;
    const int c = lane & 3;
    // ldmatrix lane addressing
    const int aRow = (lane & 7) + ((lane >> 3) & 1)*8;   // + i*16 + mB
    const int aSel = (lane >> 4)*8;                       // k-half from lane 16-31
    const int bRow = (lane & 7);                          // + j*8 + nB (lanes 0-15)
    const int bSel = (((lane & 15) >> 3) & 1)*8;          // k-half

    int cur = 0;
    for (int kt = 0; kt < nk; kt++){
        cp_wait<1>();
        __syncthreads();

        if (kt + 2 < nk){
            int nxt = cur + 2;
            if (nxt >= NSTG) nxt -= NSTG;
            const int ko = (kt+2) << 5;
            cp_async16(&As[nxt][lr][c0*8     ], Ag + ko);
            cp_async16(&As[nxt][lr][c0*8 + 16], Ag + ko + 16);
            cp_async16(&Bs[nxt][lr][c0*8     ], Bg0 + ko);
            cp_async16(&Bs[nxt][lr][c0*8 + 16], Bg0 + ko + 16);
            cp_async16(&Bs[nxt][lr + 128][c0*8     ], Bg1 + ko);
            cp_async16(&Bs[nxt][lr + 128][c0*8 + 16], Bg1 + ko + 16);
            cp_commit();
        }

        #pragma unroll
        for (int kk = 0; kk < 2; kk++){
            uint32_t af[4][4], bf[8][2];
            #pragma unroll
            for (int i = 0; i < 4; i++){
                const uint32_t addr = s2u(&As[cur][mB + i*16 + aRow][kk*16 + aSel]);
                LDSM_X4(af[i][0], af[i][1], af[i][2], af[i][3], addr);
            }
            #pragma unroll
            for (int j = 0; j < 8; j++){
                const uint32_t addr = s2u(&Bs[cur][nB + j*8 + bRow][kk*16 + bSel]);
                LDSM_X2(bf[j][0], bf[j][1], addr);
            }
            #pragma unroll
            for (int i = 0; i < 4; i++)
                #pragma unroll
                for (int j = 0; j < 8; j++)
                    mma_f16(acc[i][j], af[i][0], af[i][1], af[i][2], af[i][3],
                            bf[j][0], bf[j][1]);
        }
        cur = (cur + 1 == NSTG) ? 0 : cur + 1;
    }

    #pragma unroll
    for (int i = 0; i < 4; i++){
        const int row = bm + mB + i*16 + g;
        #pragma unroll
        for (int j = 0; j < 8; j++){
            const int col = bn + nB + j*8 + c*2;
            float v0 = acc[i][j][0], v1 = acc[i][j][1];
            float v2 = acc[i][j][2], v3 = acc[i][j][3];
            const size_t o0 = (size_t)row*N + col;
            const size_t o1 = (size_t)(row+8)*N + col;
            if (EPI == 0){
                *(__half2*)(Ch + o0) = __floats2half2_rn(v0, v1);
                *(__half2*)(Ch + o1) = __floats2half2_rn(v2, v3);
            } else if (EPI == 1){
                const float b0 = bias[col], b1 = bias[col+1];
                *(float2*)(C + o0) = make_float2(v0 + b0 + res[o0], v1 + b1 + res[o0+1]);
                *(float2*)(C + o1) = make_float2(v2 + b0 + res[o1], v3 + b1 + res[o1+1]);
            } else {
                const float b0 = bias[col], b1 = bias[col+1];
                *(__half2*)(Ch + o0) = __floats2half2_rn(gelu_tanh(v0 + b0), gelu_tanh(v1 + b1));
                *(__half2*)(Ch + o1) = __floats2half2_rn(gelu_tanh(v2 + b0), gelu_tanh(v3 + b1));
            }
        }
    }
}

// ---------------- Causal flash attention: BM=128, 256 threads, ldmatrix feed ----------------
// QP[128][HSA] Q then P; Ks[64][HSA]; Vs[64][HSA] row-major (no transpose —
// PV B-fragments come from ldmatrix.x2.trans).
#define HSA 72
__global__ __launch_bounds__(256, 2) void attn_h_kernel(const __half* __restrict__ qkv,
                                                        __half* __restrict__ oh)
{
    extern __shared__ __half sh[];
    __half* QP = sh;                    // [128][HSA]
    __half* Ks = sh + 128*HSA;          // [64][HSA]
    __half* Vs = sh + 192*HSA;          // [64][HSA]

    const int qtile = gridDim.x - 1 - blockIdx.x;
    const int bh = blockIdx.y;
    const int b = bh >> 4;
    const int h = bh & 15;
    const int tid = threadIdx.x;
    const int lane = tid & 31;
    const int warp = tid >> 5;
    const int mB = warp * 16;
    const int g = lane >> 2;
    const int c = lane & 3;
    const size_t base = (size_t)b * NSEQ * (3*DD);
    const int hoff = h * HS;
    const int qt0 = qtile * 128;

    // ldmatrix lane addressing
    const int aRow = (lane & 7) + ((lane >> 3) & 1)*8;
    const int aSel = (lane >> 4)*8;
    const int bRow = (lane & 7);
    const int bSel = (((lane & 15) >> 3) & 1)*8;
    const int vRow = (lane & 15);            // for x2.trans: rows k0..k15

    // load Q tile
    for (int i = tid; i < 1024; i += 256){
        const int row = i >> 3, ch = i & 7;
        *(uint4*)&QP[row*HSA + ch*8] =
            *(const uint4*)(qkv + base + (size_t)(qt0+row)*(3*DD) + hoff + ch*8);
    }
    __syncthreads();

    // hoist Q fragments (once) via ldmatrix; then QP becomes P
    uint32_t qa[4][4];
    #pragma unroll
    for (int kk = 0; kk < 4; kk++){
        const uint32_t addr = s2u(&QP[(mB + aRow)*HSA + kk*16 + aSel]);
        LDSM_X4(qa[kk][0], qa[kk][1], qa[kk][2], qa[kk][3], addr);
    }
    __syncthreads();

    float o[8][4] = {};
    float m0=-1e30f, m1=-1e30f, l0=0.f, l1=0.f;

    const int r0g = qt0 + mB + g;
    const int r1g = r0g + 8;
    const int njt = 2*qtile + 2;

    for (int jt = 0; jt < njt; jt++){
        __syncthreads();
        for (int i = tid; i < 512; i += 256){
            const int row = i >> 3, ch = i & 7;
            const size_t roff = base + (size_t)(jt*64+row)*(3*DD) + hoff + ch*8;
            *(uint4*)&Ks[row*HSA + ch*8] = *(const uint4*)(qkv + roff + DD);
            *(uint4*)&Vs[row*HSA + ch*8] = *(const uint4*)(qkv + roff + 2*DD);
        }
        __syncthreads();

        // S = Q K^T   (B-frags: ldmatrix non-trans on Ks[n=key][k=d])
        float s[8][4] = {};
        #pragma unroll
        for (int kk = 0; kk < 4; kk++){
            #pragma unroll
            for (int j = 0; j < 8; j++){
                uint32_t b0, b1;
                LDSM_X2(b0, b1, s2u(&Ks[(j*8 + bRow)*HSA + kk*16 + bSel]));
                mma_f16(s[j], qa[kk][0], qa[kk][1], qa[kk][2], qa[kk][3], b0, b1);
            }
        }

        const bool maskTile = (jt >= 2*qtile);
        float rm0 = -1e30f, rm1 = -1e30f;
        #pragma unroll
        for (int j = 0; j < 8; j++){
            const int col = jt*64 + j*8 + 2*c;
            #pragma unroll
            for (int t2 = 0; t2 < 2; t2++){
                float v0 = s[j][t2]*0.125f;
                float v1 = s[j][2+t2]*0.125f;
                if (maskTile){
                    if (col+t2 > r0g) v0 = -1e30f;
                    if (col+t2 > r1g) v1 = -1e30f;
                }
                s[j][t2] = v0;  s[j][2+t2] = v1;
                rm0 = fmaxf(rm0, v0); rm1 = fmaxf(rm1, v1);
            }
        }
        #pragma unroll
        for (int off = 1; off <= 2; off <<= 1){
            rm0 = fmaxf(rm0, __shfl_xor_sync(0xffffffffu, rm0, off));
            rm1 = fmaxf(rm1, __shfl_xor_sync(0xffffffffu, rm1, off));
        }
        const float mn0 = fmaxf(m0, rm0), mn1 = fmaxf(m1, rm1);
        const float alpha0 = __expf(m0 - mn0), alpha1 = __expf(m1 - mn1);
        m0 = mn0; m1 = mn1;

        float rs0 = 0.f, rs1 = 0.f;
        #pragma unroll
        for (int j = 0; j < 8; j++){
            float p0 = __expf(s[j][0] - mn0);
            float p1 = __expf(s[j][1] - mn0);
            float p2 = __expf(s[j][2] - mn1);
            float p3 = __expf(s[j][3] - mn1);
            rs0 += p0 + p1;  rs1 += p2 + p3;
            *(__half2*)&QP[(mB+g  )*HSA + j*8 + 2*c] = __floats2half2_rn(p0, p1);
            *(__half2*)&QP[(mB+g+8)*HSA + j*8 + 2*c] = __floats2half2_rn(p2, p3);
        }
        #pragma unroll
        for (int off = 1; off <= 2; off <<= 1){
            rs0 += __shfl_xor_sync(0xffffffffu, rs0, off);
            rs1 += __shfl_xor_sync(0xffffffffu, rs1, off);
        }
        l0 = l0*alpha0 + rs0;
        l1 = l1*alpha1 + rs1;

        #pragma unroll
        for (int j = 0; j < 8; j++){
            o[j][0] *= alpha0; o[j][1] *= alpha0;
            o[j][2] *= alpha1; o[j][3] *= alpha1;
        }
        __syncwarp();      // P rows are warp-private

        // O += P @ V   (A-frags via x4 on QP; B-frags via x2.trans on Vs)
        #pragma unroll
        for (int kk = 0; kk < 4; kk++){
            uint32_t a0, a1, a2, a3;
            LDSM_X4(a0, a1, a2, a3, s2u(&QP[(mB + aRow)*HSA + kk*16 + aSel]));
            #pragma unroll
            for (int j = 0; j < 8; j++){
                uint32_t b0, b1;
                LDSM_X2T(b0, b1, s2u(&Vs[(kk*16 + vRow)*HSA + j*8]));
                mma_f16(o[j], a0, a1, a2, a3, b0, b1);
            }
        }
    }

    const float inv0 = 1.0f/l0, inv1 = 1.0f/l1;
    #pragma unroll
    for (int j = 0; j < 8; j++){
        const int col = hoff + j*8 + 2*c;
        *(__half2*)(oh + (size_t)(b*NSEQ + r0g)*DD + col) =
            __floats2half2_rn(o[j][0]*inv0, o[j][1]*inv0);
        *(__half2*)(oh + (size_t)(b*NSEQ + r1g)*DD + col) =
            __floats2half2_rn(o[j][2]*inv1, o[j][3]*inv1);
    }
}

// ---------------- launch ----------------
extern "C" void kernel_launch(void* const* d_in, const int* in_sizes, int n_in,
                              void* d_out, int out_size)
{
    const float* x    = (const float*)d_in[0];
    const float* ln1s = (const float*)d_in[1];
    const float* ln1b = (const float*)d_in[2];
    const float* wqkv = (const float*)d_in[3];
    const float* wout = (const float*)d_in[4];
    const float* bout = (const float*)d_in[5];
    const float* ln2s = (const float*)d_in[6];
    const float* ln2b = (const float*)d_in[7];
    const float* w1   = (const float*)d_in[8];
    const float* b1   = (const float*)d_in[9];
    const float* w2   = (const float*)d_in[10];
    const float* b2   = (const float*)d_in[11];
    float* out = (float*)d_out;

    float *p_x1;
    __half *p_xn, *p_qkv, *p_oh, *p_xn2, *p_y;
    __half *p_wqkvh, *p_wouth, *p_w1h, *p_w2h;
    cudaGetSymbolAddress((void**)&p_xn , g_xn );
    cudaGetSymbolAddress((void**)&p_qkv, g_qkv);
    cudaGetSymbolAddress((void**)&p_oh , g_oh );
    cudaGetSymbolAddress((void**)&p_x1 , g_x1 );
    cudaGetSymbolAddress((void**)&p_xn2, g_xn2);
    cudaGetSymbolAddress((void**)&p_y  , g_y  );
    cudaGetSymbolAddress((void**)&p_wqkvh, g_wqkvh);
    cudaGetSymbolAddress((void**)&p_wouth, g_wouth);
    cudaGetSymbolAddress((void**)&p_w1h  , g_w1h  );
    cudaGetSymbolAddress((void**)&p_w2h  , g_w2h  );

    const int attn_smem = 256*HSA*sizeof(__half);                 // 36864 B
    cudaFuncSetAttribute(attn_h_kernel, cudaFuncAttributeMaxDynamicSharedMemorySize, attn_smem);
    const int fat_smem = NSTG*(TM + TN)*HSTR*sizeof(__half);      // 92160 B
    cudaFuncSetAttribute(hgemm_fat<0>, cudaFuncAttributeMaxDynamicSharedMemorySize, fat_smem);
    cudaFuncSetAttribute(hgemm_fat<1>, cudaFuncAttributeMaxDynamicSharedMemorySize, fat_smem);
    cudaFuncSetAttribute(hgemm_fat<2>, cudaFuncAttributeMaxDynamicSharedMemorySize, fat_smem);

    wtrans_all_kernel<<<8192,256>>>(wqkv, p_wqkvh, wout, p_wouth, w1, p_w1h, w2, p_w2h);

    ln_kernel<<<MM,256>>>(x, ln1s, ln1b, p_xn);
    hgemm_fat<0><<<dim3(3*DD/TN, MM/TM),256,fat_smem>>>(p_xn, p_wqkvh, nullptr, p_qkv,
                                                        MM, 3*DD, DD, nullptr, nullptr);
    attn_h_kernel<<<dim3(NSEQ/128, BB*NH),256,attn_smem>>>(p_qkv, p_oh);
    hgemm_fat<1><<<dim3(DD/TN, MM/TM),256,fat_smem>>>(p_oh, p_wouth, p_x1, nullptr,
                                                      MM, DD, DD, bout, x);
    ln_kernel<<<MM,256>>>(p_x1, ln2s, ln2b, p_xn2);
    hgemm_fat<2><<<dim3(2*DD/TN, MM/TM),256,fat_smem>>>(p_xn2, p_w1h, nullptr, p_y,
                                                        MM, 2*DD, DD, b1, nullptr);
    hgemm_fat<1><<<dim3(DD/TN, MM/TM),256,fat_smem>>>(p_y, p_w2h, out, nullptr,
                                                      MM, DD, 2*DD, b2, p_x1);
}